// round 6
// baseline (speedup 1.0000x reference)
#include <cuda_runtime.h>
#include <cuda_fp16.h>
#include <cstdint>

#define K_DIM 512
#define N_DIM 512
#define BN_EPS 1e-3f
#define KC 64
#define NKT 8              // 512/64 k-chunks
#define PITCH_B 144        // smem row pitch bytes (72 fp16)
#define AH_OFF 0
#define AL_OFF 18432
#define BH_OFF 36864
#define STAGE_SZ 55296
#define SMEM_TOTAL (2 * STAGE_SZ)

// precomputed W (fp16), transposed to [n][k]
__device__ __align__(16) __half g_Wt[N_DIM * K_DIM];
// per-rowblock completion counters (zero-init; self-resetting each launch)
__device__ int g_ctr[512];

// ---------------- helpers ---------------------------------------------------
__device__ __forceinline__ uint32_t smem_u32(const void* p) {
    uint32_t a;
    asm("{ .reg .u64 t; cvta.to.shared.u64 t, %1; cvt.u32.u64 %0, t; }" : "=r"(a) : "l"(p));
    return a;
}
__device__ __forceinline__ void cp16(uint32_t dst, const void* src) {
    asm volatile("cp.async.cg.shared.global [%0], [%1], 16;" :: "r"(dst), "l"(src));
}
#define CP_COMMIT() asm volatile("cp.async.commit_group;" ::: "memory")
#define CP_WAIT0()  asm volatile("cp.async.wait_group 0;" ::: "memory")

__device__ __forceinline__ void ldsm4(uint32_t& r0, uint32_t& r1, uint32_t& r2, uint32_t& r3,
                                      uint32_t a) {
    asm volatile("ldmatrix.sync.aligned.m8n8.x4.shared.b16 {%0,%1,%2,%3}, [%4];"
                 : "=r"(r0), "=r"(r1), "=r"(r2), "=r"(r3) : "r"(a));
}
__device__ __forceinline__ void mma16816(float* d, const uint32_t* a, uint32_t b0, uint32_t b1) {
    asm volatile("mma.sync.aligned.m16n8k16.row.col.f32.f16.f16.f32 "
                 "{%0,%1,%2,%3}, {%4,%5,%6,%7}, {%8,%9}, {%0,%1,%2,%3};"
                 : "+f"(d[0]), "+f"(d[1]), "+f"(d[2]), "+f"(d[3])
                 : "r"(a[0]), "r"(a[1]), "r"(a[2]), "r"(a[3]), "r"(b0), "r"(b1));
}
__device__ __forceinline__ uint32_t pack_f16(float x, float y) {
    return (uint32_t)__half_as_ushort(__float2half_rn(x)) |
           ((uint32_t)__half_as_ushort(__float2half_rn(y)) << 16);
}

__device__ __forceinline__ float wsumf(float v) {
#pragma unroll
    for (int o = 16; o > 0; o >>= 1) v += __shfl_xor_sync(0xffffffffu, v, o);
    return v;
}
__device__ __forceinline__ int wsumi(int v) {
#pragma unroll
    for (int o = 16; o > 0; o >>= 1) v += __shfl_xor_sync(0xffffffffu, v, o);
    return v;
}

// row-wise sparsemax (Michelot fixed point), one warp, 512 elems, in-place
__device__ __forceinline__ void sparsemax_row(float* __restrict__ row, int lane) {
    float z[16];
#pragma unroll
    for (int j = 0; j < 4; ++j) {
        const float4 v = *(const float4*)&row[lane * 4 + j * 128];
        z[j * 4 + 0] = v.x; z[j * 4 + 1] = v.y; z[j * 4 + 2] = v.z; z[j * 4 + 3] = v.w;
    }
    float s = 0.f;
#pragma unroll
    for (int i = 0; i < 16; ++i) s += z[i];
    s = wsumf(s);
    int cnt = N_DIM;
    float tau = (s - 1.0f) * (1.0f / N_DIM);
#pragma unroll 1
    for (int it = 0; it < 64; ++it) {
        float s2 = 0.f; int c2 = 0;
#pragma unroll
        for (int i = 0; i < 16; ++i)
            if (z[i] > tau) { s2 += z[i]; c2++; }
        s2 = wsumf(s2);
        c2 = wsumi(c2);
        if (c2 <= 0) break;
        const float ntau = (s2 - 1.0f) / (float)c2;
        if (c2 >= cnt) { tau = ntau; break; }
        cnt = c2;
        tau = ntau;
    }
#pragma unroll
    for (int j = 0; j < 4; ++j) {
        float4 o;
        o.x = fmaxf(z[j * 4 + 0] - tau, 0.f);
        o.y = fmaxf(z[j * 4 + 1] - tau, 0.f);
        o.z = fmaxf(z[j * 4 + 2] - tau, 0.f);
        o.w = fmaxf(z[j * 4 + 3] - tau, 0.f);
        *(float4*)&row[lane * 4 + j * 128] = o;
    }
}

// ---------------- W convert/transpose ---------------------------------------
__global__ void wconv_kernel(const float* __restrict__ W) {
    int idx = blockIdx.x * 256 + threadIdx.x;   // 1024 x 256 = 512*512
    int k = idx >> 9, n = idx & 511;
    g_Wt[n * K_DIM + k] = __float2half_rn(W[idx]);
}

// ---------------- GEMM (fp16x2) + ghost BN + priors + fused sparsemax -------
// 512 threads, 16 warps, warp tile 32x32: wm = wid&3 (rows), wn = wid>>2 (cols)
__global__ __launch_bounds__(512, 1) void gemm_bn_kernel(
    const float* __restrict__ A,
    const float* __restrict__ priors,
    const float* __restrict__ gamma,
    const float* __restrict__ beta,
    float* __restrict__ out)
{
    extern __shared__ char smem[];
    const uint32_t sb = smem_u32(smem);
    const int tid = threadIdx.x;
    const int lane = tid & 31;
    const int wid = tid >> 5;
    const int wm = wid & 3;       // rows wm*32..
    const int wn = wid >> 2;      // cols wn*32..
    const int col0 = blockIdx.x * 128;
    const int row0 = blockIdx.y * 128;

    float acc[2][4][4];
#pragma unroll
    for (int mi = 0; mi < 2; ++mi)
#pragma unroll
        for (int ni = 0; ni < 4; ++ni)
#pragma unroll
            for (int e = 0; e < 4; ++e) acc[mi][ni][e] = 0.f;

    const uint32_t a_off = (uint32_t)((lane & 15) * PITCH_B + (lane >> 4) * 16);
    const uint32_t b_off = (uint32_t)(((lane & 7) + 8 * ((lane >> 3) & 1)) * PITCH_B +
                                      (lane >> 4) * 16);

    float4 av[4];

    // ---- prologue: stage 0 ----
#pragma unroll
    for (int i = 0; i < 4; ++i) {
        int idx = tid + 512 * i;                 // 2048 float4 total
        av[i] = *(const float4*)&A[(size_t)(row0 + (idx >> 4)) * K_DIM + (idx & 15) * 4];
    }
#pragma unroll
    for (int i = 0; i < 2; ++i) {
        int idx = tid + 512 * i;                 // 1024 cp16 (B)
        int r = idx >> 3, ch = idx & 7;
        cp16(sb + BH_OFF + r * PITCH_B + ch * 16,
             g_Wt + (size_t)(col0 + r) * K_DIM + ch * 8);
    }
    CP_COMMIT();
    {
        char* sp = smem;
#pragma unroll
        for (int i = 0; i < 4; ++i) {
            int idx = tid + 512 * i;
            int r = idx >> 4, c4 = idx & 15;
            float4 v = av[i];
            uint2 hp, lp;
            hp.x = pack_f16(v.x, v.y);
            hp.y = pack_f16(v.z, v.w);
            float rx = v.x - __half2float(__float2half_rn(v.x));
            float ry = v.y - __half2float(__float2half_rn(v.y));
            float rz = v.z - __half2float(__float2half_rn(v.z));
            float rw = v.w - __half2float(__float2half_rn(v.w));
            lp.x = pack_f16(rx, ry);
            lp.y = pack_f16(rz, rw);
            *(uint2*)(sp + AH_OFF + r * PITCH_B + c4 * 8) = hp;
            *(uint2*)(sp + AL_OFF + r * PITCH_B + c4 * 8) = lp;
        }
    }
    CP_WAIT0();
    __syncthreads();

    // ---- main loop ----
    for (int kt = 0; kt < NKT; ++kt) {
        const int buf = kt & 1;
        if (kt + 1 < NKT) {
            const int kn = kt + 1;
#pragma unroll
            for (int i = 0; i < 4; ++i) {
                int idx = tid + 512 * i;
                av[i] = *(const float4*)&A[(size_t)(row0 + (idx >> 4)) * K_DIM +
                                           kn * KC + (idx & 15) * 4];
            }
            const uint32_t db = sb + (buf ^ 1) * STAGE_SZ;
#pragma unroll
            for (int i = 0; i < 2; ++i) {
                int idx = tid + 512 * i;
                int r = idx >> 3, ch = idx & 7;
                cp16(db + BH_OFF + r * PITCH_B + ch * 16,
                     g_Wt + (size_t)(col0 + r) * K_DIM + kn * KC + ch * 8);
            }
            CP_COMMIT();
        }

        // compute on stage buf
        {
            const uint32_t stg = sb + buf * STAGE_SZ;
            const uint32_t aHb = stg + AH_OFF + (wm * 32) * PITCH_B + a_off;
            const uint32_t aLb = stg + AL_OFF + (wm * 32) * PITCH_B + a_off;
            const uint32_t bHb = stg + BH_OFF + (wn * 32) * PITCH_B + b_off;
#pragma unroll
            for (int ks = 0; ks < 4; ++ks) {
                uint32_t ah[2][4], al[2][4];
                ldsm4(ah[0][0], ah[0][1], ah[0][2], ah[0][3], aHb + ks * 32);
                ldsm4(ah[1][0], ah[1][1], ah[1][2], ah[1][3], aHb + 16 * PITCH_B + ks * 32);
                ldsm4(al[0][0], al[0][1], al[0][2], al[0][3], aLb + ks * 32);
                ldsm4(al[1][0], al[1][1], al[1][2], al[1][3], aLb + 16 * PITCH_B + ks * 32);
#pragma unroll
                for (int n16 = 0; n16 < 2; ++n16) {
                    uint32_t bh[4];
                    ldsm4(bh[0], bh[1], bh[2], bh[3], bHb + n16 * 16 * PITCH_B + ks * 32);
#pragma unroll
                    for (int t = 0; t < 2; ++t) {       // pass: t=0 Ah, t=1 Al
#pragma unroll
                        for (int n8 = 0; n8 < 2; ++n8) {
#pragma unroll
                            for (int mi = 0; mi < 2; ++mi) {
                                const uint32_t* a = t ? al[mi] : ah[mi];
                                mma16816(acc[mi][n16 * 2 + n8], a, bh[n8], bh[n8 + 2]);
                            }
                        }
                    }
                }
            }
        }

        if (kt + 1 < NKT) {
            char* sp = smem + (buf ^ 1) * STAGE_SZ;
#pragma unroll
            for (int i = 0; i < 4; ++i) {
                int idx = tid + 512 * i;
                int r = idx >> 4, c4 = idx & 15;
                float4 v = av[i];
                uint2 hp, lp;
                hp.x = pack_f16(v.x, v.y);
                hp.y = pack_f16(v.z, v.w);
                float rx = v.x - __half2float(__float2half_rn(v.x));
                float ry = v.y - __half2float(__float2half_rn(v.y));
                float rz = v.z - __half2float(__float2half_rn(v.z));
                float rw = v.w - __half2float(__float2half_rn(v.w));
                lp.x = pack_f16(rx, ry);
                lp.y = pack_f16(rz, rw);
                *(uint2*)(sp + AH_OFF + r * PITCH_B + c4 * 8) = hp;
                *(uint2*)(sp + AL_OFF + r * PITCH_B + c4 * 8) = lp;
            }
            CP_WAIT0();
        }
        __syncthreads();
    }

    // ---- epilogue: ghost BN over this CTA's 128 rows, then *priors ----
    // acc layout: row = row0 + wm*32 + mi*16 + (lane>>2) + 8*h
    //             col = col0 + wn*32 + ni*8 + 2*(lane&3) + e ; acc[mi][ni][2h+e]
    float* ssum = (float*)smem;                 // [128][33]
    float* ssq  = (float*)(smem + 16896);       // [128][33]
    const int slot = wm * 8 + (lane >> 2);
#pragma unroll
    for (int ni = 0; ni < 4; ++ni) {
#pragma unroll
        for (int e = 0; e < 2; ++e) {
            float s = 0.f, q = 0.f;
#pragma unroll
            for (int mi = 0; mi < 2; ++mi)
#pragma unroll
                for (int h = 0; h < 2; ++h) {
                    float v = acc[mi][ni][2 * h + e];
                    s += v; q += v * v;
                }
            int c = wn * 32 + ni * 8 + 2 * (lane & 3) + e;
            ssum[c * 33 + slot] = s;
            ssq [c * 33 + slot] = q;
        }
    }
    __syncthreads();

    float* scales = (float*)(smem + 33792);
    float* shifts = (float*)(smem + 35840);
    if (tid < 128) {
        float s = 0.f, q = 0.f;
#pragma unroll
        for (int t = 0; t < 32; ++t) { s += ssum[tid * 33 + t]; q += ssq[tid * 33 + t]; }
        float mean = s * (1.f / 128.f);
        float var = q * (1.f / 128.f) - mean * mean;
        if (var < 0.f) var = 0.f;
        float sc = gamma[col0 + tid] * rsqrtf(var + BN_EPS);
        scales[tid] = sc;
        shifts[tid] = beta[col0 + tid] - mean * sc;
    }
    __syncthreads();

#pragma unroll
    for (int mi = 0; mi < 2; ++mi)
#pragma unroll
        for (int h = 0; h < 2; ++h) {
            int r = row0 + wm * 32 + mi * 16 + (lane >> 2) + 8 * h;
#pragma unroll
            for (int ni = 0; ni < 4; ++ni) {
                int c = wn * 32 + ni * 8 + 2 * (lane & 3);
                float2 p = *(const float2*)&priors[(size_t)r * N_DIM + col0 + c];
                float2 o;
                o.x = fmaf(acc[mi][ni][2 * h + 0], scales[c], shifts[c]) * p.x;
                o.y = fmaf(acc[mi][ni][2 * h + 1], scales[c + 1], shifts[c + 1]) * p.y;
                *(float2*)&out[(size_t)r * N_DIM + col0 + c] = o;
            }
        }

    // ---- fused finish: last of the 4 col-CTAs runs sparsemax for the block --
    __threadfence();
    __syncthreads();
    __shared__ int s_go;
    if (tid == 0) s_go = atomicAdd(&g_ctr[blockIdx.y], 1);
    __syncthreads();
    if (s_go != 3) return;
    __threadfence();   // acquire side: see peers' writes to out

    // 16 warps x 8 rows = 128 rows; data is L2-hot
#pragma unroll 1
    for (int rr = 0; rr < 8; ++rr) {
        const int r = row0 + wid * 8 + rr;
        sparsemax_row(out + (size_t)r * N_DIM, lane);
    }

    if (tid == 0) g_ctr[blockIdx.y] = 0;   // self-reset for next launch/replay
}

// ---------------------------------------------------------------------------
extern "C" void kernel_launch(void* const* d_in, const int* in_sizes, int n_in,
                              void* d_out, int out_size)
{
    const float* inputs = (const float*)d_in[0];   // [65536, 512]
    const float* priors = (const float*)d_in[1];   // [65536, 512]
    const float* Wm     = (const float*)d_in[2];   // [512, 512]
    const float* gamma  = (const float*)d_in[3];   // [512]
    const float* beta   = (const float*)d_in[4];   // [512]
    float* out = (float*)d_out;

    const int M = in_sizes[0] / K_DIM;             // 65536

    cudaFuncSetAttribute(gemm_bn_kernel, cudaFuncAttributeMaxDynamicSharedMemorySize,
                         SMEM_TOTAL);

    wconv_kernel<<<1024, 256>>>(Wm);
    gemm_bn_kernel<<<dim3(N_DIM / 128, M / 128), 512, SMEM_TOTAL>>>(
        inputs, priors, gamma, beta, out);
}

// round 8
// speedup vs baseline: 1.0768x; 1.0768x over previous
#include <cuda_runtime.h>
#include <cuda_fp16.h>
#include <cstdint>

#define K_DIM 512
#define N_DIM 512
#define M_MAX 65536
#define BN_EPS 1e-3f
#define KC 64
#define NKT 8              // 512/64 k-chunks
#define PITCH_B 144        // smem row pitch bytes (72 fp16)
#define AH_OFF 0
#define AL_OFF 18432
#define BH_OFF 36864
#define STAGE_SZ 55296
#define SMEM_TOTAL (2 * STAGE_SZ)

// precomputed operands
__device__ __align__(16) __half g_Wt[N_DIM * K_DIM];           // W fp16, [n][k]
__device__ __align__(16) __half g_A_hi[(size_t)M_MAX * K_DIM]; // A fp16 hi plane
__device__ __align__(16) __half g_A_lo[(size_t)M_MAX * K_DIM]; // A fp16 lo plane

// ---------------- helpers ---------------------------------------------------
__device__ __forceinline__ uint32_t smem_u32(const void* p) {
    uint32_t a;
    asm("{ .reg .u64 t; cvta.to.shared.u64 t, %1; cvt.u32.u64 %0, t; }" : "=r"(a) : "l"(p));
    return a;
}
__device__ __forceinline__ void cp16(uint32_t dst, const void* src) {
    asm volatile("cp.async.cg.shared.global [%0], [%1], 16;" :: "r"(dst), "l"(src));
}
#define CP_COMMIT()  asm volatile("cp.async.commit_group;" ::: "memory")
#define CP_WAIT(n)   asm volatile("cp.async.wait_group %0;" :: "n"(n) : "memory")

__device__ __forceinline__ void ldsm4(uint32_t& r0, uint32_t& r1, uint32_t& r2, uint32_t& r3,
                                      uint32_t a) {
    asm volatile("ldmatrix.sync.aligned.m8n8.x4.shared.b16 {%0,%1,%2,%3}, [%4];"
                 : "=r"(r0), "=r"(r1), "=r"(r2), "=r"(r3) : "r"(a));
}
__device__ __forceinline__ void mma16816(float* d, const uint32_t* a, uint32_t b0, uint32_t b1) {
    asm volatile("mma.sync.aligned.m16n8k16.row.col.f32.f16.f16.f32 "
                 "{%0,%1,%2,%3}, {%4,%5,%6,%7}, {%8,%9}, {%0,%1,%2,%3};"
                 : "+f"(d[0]), "+f"(d[1]), "+f"(d[2]), "+f"(d[3])
                 : "r"(a[0]), "r"(a[1]), "r"(a[2]), "r"(a[3]), "r"(b0), "r"(b1));
}
__device__ __forceinline__ uint32_t pack_f16(float x, float y) {
    return (uint32_t)__half_as_ushort(__float2half_rn(x)) |
           ((uint32_t)__half_as_ushort(__float2half_rn(y)) << 16);
}

// ---------------- W convert/transpose ---------------------------------------
__global__ void wconv_kernel(const float* __restrict__ W) {
    int idx = blockIdx.x * 256 + threadIdx.x;   // 1024 x 256 = 512*512
    int k = idx >> 9, n = idx & 511;
    g_Wt[n * K_DIM + k] = __float2half_rn(W[idx]);
}

// ---------------- A split pre-pass (streaming, memory-bound) ----------------
__global__ __launch_bounds__(256) void aconv_kernel(const float* __restrict__ A) {
    size_t i4 = (size_t)blockIdx.x * 256 + threadIdx.x;   // one float4 each
    const float4 v = *(const float4*)(A + i4 * 4);
    uint2 hp, lp;
    hp.x = pack_f16(v.x, v.y);
    hp.y = pack_f16(v.z, v.w);
    float rx = v.x - __half2float(__float2half_rn(v.x));
    float ry = v.y - __half2float(__float2half_rn(v.y));
    float rz = v.z - __half2float(__float2half_rn(v.z));
    float rw = v.w - __half2float(__float2half_rn(v.w));
    lp.x = pack_f16(rx, ry);
    lp.y = pack_f16(rz, rw);
    *(uint2*)((char*)g_A_hi + i4 * 8) = hp;
    *(uint2*)((char*)g_A_lo + i4 * 8) = lp;
}

// ---------------- GEMM (fp16x2 HMMA) + ghost BN + priors --------------------
// 512 threads, 16 warps, warp tile 32x32: wm = wid&3 (rows), wn = wid>>2 (cols)
__global__ __launch_bounds__(512, 1) void gemm_bn_kernel(
    const float* __restrict__ priors,
    const float* __restrict__ gamma,
    const float* __restrict__ beta,
    float* __restrict__ out)
{
    extern __shared__ char smem[];
    const uint32_t sb = smem_u32(smem);
    const int tid = threadIdx.x;
    const int lane = tid & 31;
    const int wid = tid >> 5;
    const int wm = wid & 3;       // rows wm*32..
    const int wn = wid >> 2;      // cols wn*32..
    const int col0 = blockIdx.x * 128;
    const int row0 = blockIdx.y * 128;

    float acc[2][4][4];
#pragma unroll
    for (int mi = 0; mi < 2; ++mi)
#pragma unroll
        for (int ni = 0; ni < 4; ++ni)
#pragma unroll
            for (int e = 0; e < 4; ++e) acc[mi][ni][e] = 0.f;

    const uint32_t a_off = (uint32_t)((lane & 15) * PITCH_B + (lane >> 4) * 16);
    const uint32_t b_off = (uint32_t)(((lane & 7) + 8 * ((lane >> 3) & 1)) * PITCH_B +
                                      (lane >> 4) * 16);

    // per-thread load coordinates: idx in [0,1024): r = idx>>3, ch = idx&7
    const int l_r  = (tid + 0)   >> 3, l_c  = tid & 7;
    const int l_r2 = (tid + 512) >> 3, l_c2 = (tid + 512) & 7;

    // ---- stage loader (pure cp.async, no register staging) ----
    auto load_stage = [&](int kt, int buf) {
        const uint32_t db = sb + buf * STAGE_SZ;
        const size_t ka = (size_t)kt * KC;
        const __half* ah = g_A_hi + (size_t)(row0 + l_r)  * K_DIM + ka + l_c  * 8;
        const __half* ah2= g_A_hi + (size_t)(row0 + l_r2) * K_DIM + ka + l_c2 * 8;
        const __half* al = g_A_lo + (size_t)(row0 + l_r)  * K_DIM + ka + l_c  * 8;
        const __half* al2= g_A_lo + (size_t)(row0 + l_r2) * K_DIM + ka + l_c2 * 8;
        const __half* bw = g_Wt   + (size_t)(col0 + l_r)  * K_DIM + ka + l_c  * 8;
        const __half* bw2= g_Wt   + (size_t)(col0 + l_r2) * K_DIM + ka + l_c2 * 8;
        cp16(db + AH_OFF + l_r  * PITCH_B + l_c  * 16, ah);
        cp16(db + AH_OFF + l_r2 * PITCH_B + l_c2 * 16, ah2);
        cp16(db + AL_OFF + l_r  * PITCH_B + l_c  * 16, al);
        cp16(db + AL_OFF + l_r2 * PITCH_B + l_c2 * 16, al2);
        cp16(db + BH_OFF + l_r  * PITCH_B + l_c  * 16, bw);
        cp16(db + BH_OFF + l_r2 * PITCH_B + l_c2 * 16, bw2);
        CP_COMMIT();
    };

    // ---- prologue ----
    load_stage(0, 0);
    load_stage(1, 1);

    // ---- main loop ----
    for (int kt = 0; kt < NKT; ++kt) {
        const int buf = kt & 1;
        // pending groups at this point: stage kt (oldest) and possibly kt+1.
        // wait until <=1 pending  ==> stage kt complete. Last iter: wait all.
        if (kt + 1 < NKT) CP_WAIT(1);
        else              CP_WAIT(0);
        __syncthreads();

        // compute on stage buf
        {
            const uint32_t stg = sb + buf * STAGE_SZ;
            const uint32_t aHb = stg + AH_OFF + (wm * 32) * PITCH_B + a_off;
            const uint32_t aLb = stg + AL_OFF + (wm * 32) * PITCH_B + a_off;
            const uint32_t bHb = stg + BH_OFF + (wn * 32) * PITCH_B + b_off;
#pragma unroll
            for (int ks = 0; ks < 4; ++ks) {
                uint32_t ah[2][4], al[2][4];
                ldsm4(ah[0][0], ah[0][1], ah[0][2], ah[0][3], aHb + ks * 32);
                ldsm4(ah[1][0], ah[1][1], ah[1][2], ah[1][3], aHb + 16 * PITCH_B + ks * 32);
                ldsm4(al[0][0], al[0][1], al[0][2], al[0][3], aLb + ks * 32);
                ldsm4(al[1][0], al[1][1], al[1][2], al[1][3], aLb + 16 * PITCH_B + ks * 32);
#pragma unroll
                for (int n16 = 0; n16 < 2; ++n16) {
                    uint32_t bh[4];
                    ldsm4(bh[0], bh[1], bh[2], bh[3], bHb + n16 * 16 * PITCH_B + ks * 32);
#pragma unroll
                    for (int t = 0; t < 2; ++t) {       // pass: t=0 Ah, t=1 Al
#pragma unroll
                        for (int n8 = 0; n8 < 2; ++n8) {
#pragma unroll
                            for (int mi = 0; mi < 2; ++mi) {
                                const uint32_t* a = t ? al[mi] : ah[mi];
                                mma16816(acc[mi][n16 * 2 + n8], a, bh[n8], bh[n8 + 2]);
                            }
                        }
                    }
                }
            }
        }
        __syncthreads();                 // stage buf free before refill
        if (kt + 2 < NKT) load_stage(kt + 2, buf);
    }

    // ---- epilogue: ghost BN over this CTA's 128 rows, then *priors ----
    // acc layout: row = row0 + wm*32 + mi*16 + (lane>>2) + 8*h
    //             col = col0 + wn*32 + ni*8 + 2*(lane&3) + e ; acc[mi][ni][2h+e]
    float* ssum = (float*)smem;                 // [128][33]
    float* ssq  = (float*)(smem + 16896);       // [128][33]
    const int slot = wm * 8 + (lane >> 2);
#pragma unroll
    for (int ni = 0; ni < 4; ++ni) {
#pragma unroll
        for (int e = 0; e < 2; ++e) {
            float s = 0.f, q = 0.f;
#pragma unroll
            for (int mi = 0; mi < 2; ++mi)
#pragma unroll
                for (int h = 0; h < 2; ++h) {
                    float v = acc[mi][ni][2 * h + e];
                    s += v; q += v * v;
                }
            int c = wn * 32 + ni * 8 + 2 * (lane & 3) + e;
            ssum[c * 33 + slot] = s;
            ssq [c * 33 + slot] = q;
        }
    }
    __syncthreads();

    float* scales = (float*)(smem + 33792);
    float* shifts = (float*)(smem + 35840);
    if (tid < 128) {
        float s = 0.f, q = 0.f;
#pragma unroll
        for (int t = 0; t < 32; ++t) { s += ssum[tid * 33 + t]; q += ssq[tid * 33 + t]; }
        float mean = s * (1.f / 128.f);
        float var = q * (1.f / 128.f) - mean * mean;
        if (var < 0.f) var = 0.f;
        float sc = gamma[col0 + tid] * rsqrtf(var + BN_EPS);
        scales[tid] = sc;
        shifts[tid] = beta[col0 + tid] - mean * sc;
    }
    __syncthreads();

#pragma unroll
    for (int mi = 0; mi < 2; ++mi)
#pragma unroll
        for (int h = 0; h < 2; ++h) {
            int r = row0 + wm * 32 + mi * 16 + (lane >> 2) + 8 * h;
#pragma unroll
            for (int ni = 0; ni < 4; ++ni) {
                int c = wn * 32 + ni * 8 + 2 * (lane & 3);
                float2 p = *(const float2*)&priors[(size_t)r * N_DIM + col0 + c];
                float2 o;
                o.x = fmaf(acc[mi][ni][2 * h + 0], scales[c], shifts[c]) * p.x;
                o.y = fmaf(acc[mi][ni][2 * h + 1], scales[c + 1], shifts[c + 1]) * p.y;
                *(float2*)&out[(size_t)r * N_DIM + col0 + c] = o;
            }
        }
}

// ---------------- sparsemax ---------------------------------------------------
__device__ __forceinline__ float wsumf(float v) {
#pragma unroll
    for (int o = 16; o > 0; o >>= 1) v += __shfl_xor_sync(0xffffffffu, v, o);
    return v;
}
__device__ __forceinline__ int wsumi(int v) {
#pragma unroll
    for (int o = 16; o > 0; o >>= 1) v += __shfl_xor_sync(0xffffffffu, v, o);
    return v;
}

__global__ __launch_bounds__(256) void sparsemax_kernel(float* __restrict__ u, int M)
{
    const int gwarp = (blockIdx.x * blockDim.x + threadIdx.x) >> 5;
    const int lane  = threadIdx.x & 31;
    if (gwarp >= M) return;
    float* row = u + (size_t)gwarp * N_DIM;

    float z[16];
#pragma unroll
    for (int j = 0; j < 4; ++j) {
        const float4 v = *(const float4*)&row[lane * 4 + j * 128];
        z[j * 4 + 0] = v.x; z[j * 4 + 1] = v.y; z[j * 4 + 2] = v.z; z[j * 4 + 3] = v.w;
    }

    float s = 0.f;
#pragma unroll
    for (int i = 0; i < 16; ++i) s += z[i];
    s = wsumf(s);

    int   cnt = N_DIM;
    float tau = (s - 1.0f) * (1.0f / N_DIM);

#pragma unroll 1
    for (int it = 0; it < 64; ++it) {
        float s2 = 0.f; int c2 = 0;
#pragma unroll
        for (int i = 0; i < 16; ++i)
            if (z[i] > tau) { s2 += z[i]; c2++; }
        s2 = wsumf(s2);
        c2 = wsumi(c2);
        if (c2 <= 0) break;
        const float ntau = (s2 - 1.0f) / (float)c2;
        if (c2 >= cnt) { tau = ntau; break; }
        cnt = c2;
        tau = ntau;
    }

#pragma unroll
    for (int j = 0; j < 4; ++j) {
        float4 o;
        o.x = fmaxf(z[j * 4 + 0] - tau, 0.f);
        o.y = fmaxf(z[j * 4 + 1] - tau, 0.f);
        o.z = fmaxf(z[j * 4 + 2] - tau, 0.f);
        o.w = fmaxf(z[j * 4 + 3] - tau, 0.f);
        *(float4*)&row[lane * 4 + j * 128] = o;
    }
}

// ---------------------------------------------------------------------------
extern "C" void kernel_launch(void* const* d_in, const int* in_sizes, int n_in,
                              void* d_out, int out_size)
{
    const float* inputs = (const float*)d_in[0];   // [65536, 512]
    const float* priors = (const float*)d_in[1];   // [65536, 512]
    const float* Wm     = (const float*)d_in[2];   // [512, 512]
    const float* gamma  = (const float*)d_in[3];   // [512]
    const float* beta   = (const float*)d_in[4];   // [512]
    float* out = (float*)d_out;

    const int M = in_sizes[0] / K_DIM;             // 65536

    cudaFuncSetAttribute(gemm_bn_kernel, cudaFuncAttributeMaxDynamicSharedMemorySize,
                         SMEM_TOTAL);

    wconv_kernel<<<1024, 256>>>(Wm);
    aconv_kernel<<<(int)(((size_t)M * K_DIM / 4) / 256), 256>>>(inputs);
    gemm_bn_kernel<<<dim3(N_DIM / 128, M / 128), 512, SMEM_TOTAL>>>(
        priors, gamma, beta, out);

    const int blocks = (M * 32 + 255) / 256;
    sparsemax_kernel<<<blocks, 256>>>(out, M);
}

// round 9
// speedup vs baseline: 1.5702x; 1.4582x over previous
#include <cuda_runtime.h>
#include <cuda_fp16.h>
#include <cstdint>

#define K_DIM 512
#define N_DIM 512
#define BN_EPS 1e-3f
#define KC 64
#define NKT 8              // 512/64 k-chunks
#define PITCH_B 144        // smem row pitch bytes (72 fp16)
#define A_OFF 0
#define B_OFF 18432
#define STAGE_SZ 36864
#define SMEM_TOTAL (2 * STAGE_SZ)

// precomputed W (fp16), transposed to [n][k]
__device__ __align__(16) __half g_Wt[N_DIM * K_DIM];

// ---------------- helpers ---------------------------------------------------
__device__ __forceinline__ uint32_t smem_u32(const void* p) {
    uint32_t a;
    asm("{ .reg .u64 t; cvta.to.shared.u64 t, %1; cvt.u32.u64 %0, t; }" : "=r"(a) : "l"(p));
    return a;
}
__device__ __forceinline__ void cp16(uint32_t dst, const void* src) {
    asm volatile("cp.async.cg.shared.global [%0], [%1], 16;" :: "r"(dst), "l"(src));
}
#define CP_COMMIT() asm volatile("cp.async.commit_group;" ::: "memory")
#define CP_WAIT0()  asm volatile("cp.async.wait_group 0;" ::: "memory")

__device__ __forceinline__ void ldsm4(uint32_t& r0, uint32_t& r1, uint32_t& r2, uint32_t& r3,
                                      uint32_t a) {
    asm volatile("ldmatrix.sync.aligned.m8n8.x4.shared.b16 {%0,%1,%2,%3}, [%4];"
                 : "=r"(r0), "=r"(r1), "=r"(r2), "=r"(r3) : "r"(a));
}
__device__ __forceinline__ void mma16816(float* d, const uint32_t* a, uint32_t b0, uint32_t b1) {
    asm volatile("mma.sync.aligned.m16n8k16.row.col.f32.f16.f16.f32 "
                 "{%0,%1,%2,%3}, {%4,%5,%6,%7}, {%8,%9}, {%0,%1,%2,%3};"
                 : "+f"(d[0]), "+f"(d[1]), "+f"(d[2]), "+f"(d[3])
                 : "r"(a[0]), "r"(a[1]), "r"(a[2]), "r"(a[3]), "r"(b0), "r"(b1));
}
__device__ __forceinline__ uint32_t pack_f16(float x, float y) {
    return (uint32_t)__half_as_ushort(__float2half_rn(x)) |
           ((uint32_t)__half_as_ushort(__float2half_rn(y)) << 16);
}

// ---------------- W convert/transpose ---------------------------------------
__global__ void wconv_kernel(const float* __restrict__ W) {
    int idx = blockIdx.x * 256 + threadIdx.x;   // 1024 x 256 = 512*512
    int k = idx >> 9, n = idx & 511;
    g_Wt[n * K_DIM + k] = __float2half_rn(W[idx]);
}

// ---------------- GEMM (fp16 single pass HMMA) + ghost BN + priors ----------
// 512 threads, 16 warps, warp tile 32x32: wm = wid&3 (rows), wn = wid>>2 (cols)
__global__ __launch_bounds__(512, 1) void gemm_bn_kernel(
    const float* __restrict__ A,
    const float* __restrict__ priors,
    const float* __restrict__ gamma,
    const float* __restrict__ beta,
    float* __restrict__ out)
{
    extern __shared__ char smem[];
    const uint32_t sb = smem_u32(smem);
    const int tid = threadIdx.x;
    const int lane = tid & 31;
    const int wid = tid >> 5;
    const int wm = wid & 3;       // rows wm*32..
    const int wn = wid >> 2;      // cols wn*32..
    const int col0 = blockIdx.x * 128;
    const int row0 = blockIdx.y * 128;

    float acc[2][4][4];
#pragma unroll
    for (int mi = 0; mi < 2; ++mi)
#pragma unroll
        for (int ni = 0; ni < 4; ++ni)
#pragma unroll
            for (int e = 0; e < 4; ++e) acc[mi][ni][e] = 0.f;

    const uint32_t a_off = (uint32_t)((lane & 15) * PITCH_B + (lane >> 4) * 16);
    const uint32_t b_off = (uint32_t)(((lane & 7) + 8 * ((lane >> 3) & 1)) * PITCH_B +
                                      (lane >> 4) * 16);

    float4 av[4];

    // ---- prologue: stage 0 ----
#pragma unroll
    for (int i = 0; i < 4; ++i) {
        int idx = tid + 512 * i;                 // 2048 float4 total (A 128x64 fp32)
        av[i] = *(const float4*)&A[(size_t)(row0 + (idx >> 4)) * K_DIM + (idx & 15) * 4];
    }
#pragma unroll
    for (int i = 0; i < 2; ++i) {
        int idx = tid + 512 * i;                 // 1024 cp16 (B 128x64 fp16)
        int r = idx >> 3, ch = idx & 7;
        cp16(sb + B_OFF + r * PITCH_B + ch * 16,
             g_Wt + (size_t)(col0 + r) * K_DIM + ch * 8);
    }
    CP_COMMIT();
    {
        char* sp = smem;
#pragma unroll
        for (int i = 0; i < 4; ++i) {
            int idx = tid + 512 * i;
            int r = idx >> 4, c4 = idx & 15;
            float4 v = av[i];
            uint2 hp;
            hp.x = pack_f16(v.x, v.y);
            hp.y = pack_f16(v.z, v.w);
            *(uint2*)(sp + A_OFF + r * PITCH_B + c4 * 8) = hp;
        }
    }
    CP_WAIT0();
    __syncthreads();

    // ---- main loop ----
    for (int kt = 0; kt < NKT; ++kt) {
        const int buf = kt & 1;
        if (kt + 1 < NKT) {
            const int kn = kt + 1;
#pragma unroll
            for (int i = 0; i < 4; ++i) {
                int idx = tid + 512 * i;
                av[i] = *(const float4*)&A[(size_t)(row0 + (idx >> 4)) * K_DIM +
                                           kn * KC + (idx & 15) * 4];
            }
            const uint32_t db = sb + (buf ^ 1) * STAGE_SZ;
#pragma unroll
            for (int i = 0; i < 2; ++i) {
                int idx = tid + 512 * i;
                int r = idx >> 3, ch = idx & 7;
                cp16(db + B_OFF + r * PITCH_B + ch * 16,
                     g_Wt + (size_t)(col0 + r) * K_DIM + kn * KC + ch * 8);
            }
            CP_COMMIT();
        }

        // compute on stage buf
        {
            const uint32_t stg = sb + buf * STAGE_SZ;
            const uint32_t aB = stg + A_OFF + (wm * 32) * PITCH_B + a_off;
            const uint32_t bB = stg + B_OFF + (wn * 32) * PITCH_B + b_off;
#pragma unroll
            for (int ks = 0; ks < 4; ++ks) {
                uint32_t ah[2][4];
                ldsm4(ah[0][0], ah[0][1], ah[0][2], ah[0][3], aB + ks * 32);
                ldsm4(ah[1][0], ah[1][1], ah[1][2], ah[1][3], aB + 16 * PITCH_B + ks * 32);
#pragma unroll
                for (int n16 = 0; n16 < 2; ++n16) {
                    uint32_t bh[4];
                    ldsm4(bh[0], bh[1], bh[2], bh[3], bB + n16 * 16 * PITCH_B + ks * 32);
#pragma unroll
                    for (int n8 = 0; n8 < 2; ++n8) {
#pragma unroll
                        for (int mi = 0; mi < 2; ++mi)
                            mma16816(acc[mi][n16 * 2 + n8], ah[mi], bh[n8], bh[n8 + 2]);
                    }
                }
            }
        }

        if (kt + 1 < NKT) {
            char* sp = smem + (buf ^ 1) * STAGE_SZ;
#pragma unroll
            for (int i = 0; i < 4; ++i) {
                int idx = tid + 512 * i;
                int r = idx >> 4, c4 = idx & 15;
                float4 v = av[i];
                uint2 hp;
                hp.x = pack_f16(v.x, v.y);
                hp.y = pack_f16(v.z, v.w);
                *(uint2*)(sp + A_OFF + r * PITCH_B + c4 * 8) = hp;
            }
            CP_WAIT0();
        }
        __syncthreads();
    }

    // ---- epilogue: ghost BN over this CTA's 128 rows, then *priors ----
    // acc layout: row = row0 + wm*32 + mi*16 + (lane>>2) + 8*h
    //             col = col0 + wn*32 + ni*8 + 2*(lane&3) + e ; acc[mi][ni][2h+e]
    float* ssum = (float*)smem;                 // [128][33]
    float* ssq  = (float*)(smem + 16896);       // [128][33]
    const int slot = wm * 8 + (lane >> 2);
#pragma unroll
    for (int ni = 0; ni < 4; ++ni) {
#pragma unroll
        for (int e = 0; e < 2; ++e) {
            float s = 0.f, q = 0.f;
#pragma unroll
            for (int mi = 0; mi < 2; ++mi)
#pragma unroll
                for (int h = 0; h < 2; ++h) {
                    float v = acc[mi][ni][2 * h + e];
                    s += v; q += v * v;
                }
            int c = wn * 32 + ni * 8 + 2 * (lane & 3) + e;
            ssum[c * 33 + slot] = s;
            ssq [c * 33 + slot] = q;
        }
    }
    __syncthreads();

    float* scales = (float*)(smem + 33792);
    float* shifts = (float*)(smem + 35840);
    if (tid < 128) {
        float s = 0.f, q = 0.f;
#pragma unroll
        for (int t = 0; t < 32; ++t) { s += ssum[tid * 33 + t]; q += ssq[tid * 33 + t]; }
        float mean = s * (1.f / 128.f);
        float var = q * (1.f / 128.f) - mean * mean;
        if (var < 0.f) var = 0.f;
        float sc = gamma[col0 + tid] * rsqrtf(var + BN_EPS);
        scales[tid] = sc;
        shifts[tid] = beta[col0 + tid] - mean * sc;
    }
    __syncthreads();

#pragma unroll
    for (int mi = 0; mi < 2; ++mi)
#pragma unroll
        for (int h = 0; h < 2; ++h) {
            int r = row0 + wm * 32 + mi * 16 + (lane >> 2) + 8 * h;
#pragma unroll
            for (int ni = 0; ni < 4; ++ni) {
                int c = wn * 32 + ni * 8 + 2 * (lane & 3);
                float2 p = *(const float2*)&priors[(size_t)r * N_DIM + col0 + c];
                float2 o;
                o.x = fmaf(acc[mi][ni][2 * h + 0], scales[c], shifts[c]) * p.x;
                o.y = fmaf(acc[mi][ni][2 * h + 1], scales[c + 1], shifts[c + 1]) * p.y;
                *(float2*)&out[(size_t)r * N_DIM + col0 + c] = o;
            }
        }
}

// ---------------- sparsemax ---------------------------------------------------
__device__ __forceinline__ float wsumf(float v) {
#pragma unroll
    for (int o = 16; o > 0; o >>= 1) v += __shfl_xor_sync(0xffffffffu, v, o);
    return v;
}
__device__ __forceinline__ int wsumi(int v) {
#pragma unroll
    for (int o = 16; o > 0; o >>= 1) v += __shfl_xor_sync(0xffffffffu, v, o);
    return v;
}

__global__ __launch_bounds__(256) void sparsemax_kernel(float* __restrict__ u, int M)
{
    const int gwarp = (blockIdx.x * blockDim.x + threadIdx.x) >> 5;
    const int lane  = threadIdx.x & 31;
    if (gwarp >= M) return;
    float* row = u + (size_t)gwarp * N_DIM;

    float z[16];
#pragma unroll
    for (int j = 0; j < 4; ++j) {
        const float4 v = *(const float4*)&row[lane * 4 + j * 128];
        z[j * 4 + 0] = v.x; z[j * 4 + 1] = v.y; z[j * 4 + 2] = v.z; z[j * 4 + 3] = v.w;
    }

    float s = 0.f;
#pragma unroll
    for (int i = 0; i < 16; ++i) s += z[i];
    s = wsumf(s);

    int   cnt = N_DIM;
    float tau = (s - 1.0f) * (1.0f / N_DIM);

#pragma unroll 1
    for (int it = 0; it < 64; ++it) {
        float s2 = 0.f; int c2 = 0;
#pragma unroll
        for (int i = 0; i < 16; ++i)
            if (z[i] > tau) { s2 += z[i]; c2++; }
        s2 = wsumf(s2);
        c2 = wsumi(c2);
        if (c2 <= 0) break;
        const float ntau = (s2 - 1.0f) / (float)c2;
        if (c2 >= cnt) { tau = ntau; break; }
        cnt = c2;
        tau = ntau;
    }

#pragma unroll
    for (int j = 0; j < 4; ++j) {
        float4 o;
        o.x = fmaxf(z[j * 4 + 0] - tau, 0.f);
        o.y = fmaxf(z[j * 4 + 1] - tau, 0.f);
        o.z = fmaxf(z[j * 4 + 2] - tau, 0.f);
        o.w = fmaxf(z[j * 4 + 3] - tau, 0.f);
        *(float4*)&row[lane * 4 + j * 128] = o;
    }
}

// ---------------------------------------------------------------------------
extern "C" void kernel_launch(void* const* d_in, const int* in_sizes, int n_in,
                              void* d_out, int out_size)
{
    const float* inputs = (const float*)d_in[0];   // [65536, 512]
    const float* priors = (const float*)d_in[1];   // [65536, 512]
    const float* Wm     = (const float*)d_in[2];   // [512, 512]
    const float* gamma  = (const float*)d_in[3];   // [512]
    const float* beta   = (const float*)d_in[4];   // [512]
    float* out = (float*)d_out;

    const int M = in_sizes[0] / K_DIM;             // 65536

    cudaFuncSetAttribute(gemm_bn_kernel, cudaFuncAttributeMaxDynamicSharedMemorySize,
                         SMEM_TOTAL);

    wconv_kernel<<<1024, 256>>>(Wm);
    gemm_bn_kernel<<<dim3(N_DIM / 128, M / 128), 512, SMEM_TOTAL>>>(
        inputs, priors, gamma, beta, out);

    const int blocks = (M * 32 + 255) / 256;
    sparsemax_kernel<<<blocks, 256>>>(out, M);
}